// round 2
// baseline (speedup 1.0000x reference)
#include <cuda_runtime.h>
#include <cstddef>

typedef unsigned long long ull;

#define Tn 10
#define Bn 4
#define Cc 64
#define Hh 64
#define Ww 64
#define HWp 4096
#define RS 20                 // smem row stride

// kA: 16x16 tile, 18-row halo
#define ICS_A 360             // 18*RS
#define SM_IN_A (64*ICS_A)    // 23040 floats
// kB: 16x8 tile, 10-row halo
#define ICS_B 200             // 10*RS
#define SM_IN_B (64*ICS_B)    // 12800 floats

#define SW_ULL 2304           // 32 oc * 72 (icl*9+tap), duplicated weights
#define SMEM_A_BYTES (SM_IN_A*4 + SW_ULL*8)   // 110592
#define SMEM_B_BYTES (SM_IN_B*4 + SW_ULL*8)   // 69632

// Recurrent state + inter-kernel scratch (allocation-free device globals)
__device__ float g_prev_y [Bn*Cc*HWp];
__device__ float g_h      [Bn*Cc*HWp];
__device__ float g_gate_in[Bn*Cc*HWp];
__device__ float g_upd    [Bn*Cc*HWp];
__device__ float g_thr    [Bn*HWp];

__device__ __forceinline__ float sigmoidf_(float x) { return 1.0f / (1.0f + __expf(-x)); }

__device__ __forceinline__ ull pack2(float lo, float hi) {
    ull p;
    asm("mov.b64 %0, {%1, %2};" : "=l"(p) : "f"(lo), "f"(hi));
    return p;
}
__device__ __forceinline__ void unpack2(ull p, float& lo, float& hi) {
    asm("mov.b64 {%0, %1}, %2;" : "=f"(lo), "=f"(hi) : "l"(p));
}
__device__ __forceinline__ void ffma2(ull& d, ull a, ull b) {
    asm("fma.rn.f32x2 %0, %1, %2, %0;" : "+l"(d) : "l"(a), "l"(b));
}

// ---------------------------------------------------------------------------
// Kernel A: rz = conv3x3(prev_y, w_rz) + b_rz (128 gate channels + thr in grp0)
// grid (16 tiles, 4 oc-groups, 4 batch), 256 threads
// ---------------------------------------------------------------------------
__global__ void __launch_bounds__(256, 2)
kA(const float* __restrict__ xt, const float* __restrict__ w_rz,
   const float* __restrict__ b_rz, int t)
{
    extern __shared__ float smem[];
    float* s_in = smem;
    ull*   s_w2 = (ull*)(smem + SM_IN_A);

    const int tid  = threadIdx.x;
    const int tile = blockIdx.x;   // 0..15
    const int grp  = blockIdx.y;   // 0..3
    const int b    = blockIdx.z;
    const int ty0  = (tile >> 2) * 16;
    const int tx0  = (tile & 3) * 16;

    if (t > 0) {
        // 18x18 halo, all 64 ic
        for (int idx = tid; idx < 64 * 324; idx += 256) {
            int ic  = idx / 324;
            int rem = idx - ic * 324;
            int r   = rem / 18;
            int cc  = rem - r * 18;
            int gy  = ty0 + r - 1;
            int gx  = tx0 + cc - 1;
            float v = 0.0f;
            if (gy >= 0 && gy < Hh && gx >= 0 && gx < Ww)
                v = g_prev_y[((b * Cc + ic) * Hh + gy) * Ww + gx];
            s_in[ic * ICS_A + r * RS + cc] = v;
        }
    }

    const int oc_base = grp * 32;
    const int pixg = tid & 63;
    const int ocq  = tid >> 6;           // 0..3
    const int px   = pixg & 15;
    const int pyb  = (pixg >> 4) << 2;   // 0,4,8,12

    ull acc2[8][2];
    #pragma unroll
    for (int k = 0; k < 8; k++) { acc2[k][0] = 0ull; acc2[k][1] = 0ull; }

    if (t > 0) {
        for (int cc0 = 0; cc0 < 64; cc0 += 8) {
            __syncthreads();
            for (int i = tid; i < SW_ULL; i += 256) {
                int ocl  = i / 72;
                int rest = i - ocl * 72;
                float w  = w_rz[(oc_base + ocl) * 576 + cc0 * 9 + rest];
                s_w2[i] = pack2(w, w);
            }
            __syncthreads();
            #pragma unroll
            for (int icl = 0; icl < 8; icl++) {
                const float* sin = s_in + (cc0 + icl) * ICS_A + pyb * RS + px;
                const ull*   sw  = s_w2 + ocq * (8 * 72) + icl * 9;
                #pragma unroll
                for (int dx = 0; dx < 3; dx++) {
                    float xr[6];
                    #pragma unroll
                    for (int r = 0; r < 6; r++) xr[r] = sin[r * RS + dx];
                    ull xp[3][2];
                    #pragma unroll
                    for (int dy = 0; dy < 3; dy++) {
                        xp[dy][0] = pack2(xr[dy],     xr[dy + 1]);
                        xp[dy][1] = pack2(xr[dy + 2], xr[dy + 3]);
                    }
                    #pragma unroll
                    for (int dy = 0; dy < 3; dy++) {
                        #pragma unroll
                        for (int k = 0; k < 8; k++) {
                            ull wp = sw[k * 72 + dy * 3 + dx];
                            ffma2(acc2[k][0], xp[dy][0], wp);
                            ffma2(acc2[k][1], xp[dy][1], wp);
                        }
                    }
                }
            }
        }
    }

    // Epilogue: gates
    #pragma unroll
    for (int k = 0; k < 8; k++) {
        int oc = oc_base + ocq * 8 + k;
        float bias = b_rz[oc];
        #pragma unroll
        for (int j = 0; j < 2; j++) {
            float a0, a1;
            unpack2(acc2[k][j], a0, a1);
            float av[2] = {a0, a1};
            #pragma unroll
            for (int s = 0; s < 2; s++) {
                int i   = 2 * j + s;
                int gy  = ty0 + pyb + i;
                int gx  = tx0 + px;
                int pix = gy * Ww + gx;
                float xi = xt[((((size_t)t * Bn + b) * 192) + oc) * HWp + pix];
                float sg = sigmoidf_(av[s] + bias + xi);
                if (oc < 64) {
                    g_upd[(b * Cc + oc) * HWp + pix] = sg;
                } else {
                    int c = oc - 64;
                    float py = 0.0f;
                    if (t > 0)
                        py = s_in[c * ICS_A + (pyb + i + 1) * RS + (px + 1)];
                    g_gate_in[(b * Cc + c) * HWp + pix] = py * sg;
                }
            }
        }
    }

    // Threshold channel (oc 128) folded into grp 0
    if (grp == 0) {
        float* s_wf = (float*)s_w2;
        float acc = 0.0f;
        const int px1 = tid & 15, py1 = tid >> 4;
        if (t > 0) {
            __syncthreads();
            for (int i = tid; i < 576; i += 256)
                s_wf[i] = w_rz[128 * 576 + i];
            __syncthreads();
            float a0 = 0.f, a1 = 0.f, a2 = 0.f, a3 = 0.f;
            for (int ic = 0; ic < 64; ic++) {
                const float* sin = s_in + ic * ICS_A + py1 * RS + px1;
                const float* sw  = s_wf + ic * 9;
                a0 += sw[0] * sin[0];
                a1 += sw[1] * sin[1];
                a2 += sw[2] * sin[2];
                a3 += sw[3] * sin[RS + 0];
                a0 += sw[4] * sin[RS + 1];
                a1 += sw[5] * sin[RS + 2];
                a2 += sw[6] * sin[2 * RS + 0];
                a3 += sw[7] * sin[2 * RS + 1];
                a0 += sw[8] * sin[2 * RS + 2];
            }
            acc = (a0 + a1) + (a2 + a3);
        }
        g_thr[b * HWp + (ty0 + py1) * Ww + (tx0 + px1)] = sigmoidf_(acc + b_rz[128]);
    }
}

// ---------------------------------------------------------------------------
// Kernel B: f = conv3x3(gate_in, w_f) + b_f + xi_f; GRU update + spike + out
// grid (32 tiles 16x8, 2 oc-groups, 4 batch), 128 threads
// ---------------------------------------------------------------------------
__global__ void __launch_bounds__(128, 3)
kB(const float* __restrict__ xt, const float* __restrict__ w_f,
   const float* __restrict__ b_f, float* __restrict__ out, int t)
{
    extern __shared__ float smem[];
    float* s_in = smem;
    ull*   s_w2 = (ull*)(smem + SM_IN_B);

    const int tid  = threadIdx.x;
    const int tile = blockIdx.x;   // 0..31
    const int grp  = blockIdx.y;   // 0..1
    const int b    = blockIdx.z;
    const int ty0  = (tile >> 2) * 8;
    const int tx0  = (tile & 3) * 16;

    // 10x18 halo, all 64 ic (gate_in valid even at t=0)
    for (int idx = tid; idx < 64 * 180; idx += 128) {
        int ic  = idx / 180;
        int rem = idx - ic * 180;
        int r   = rem / 18;
        int cc  = rem - r * 18;
        int gy  = ty0 + r - 1;
        int gx  = tx0 + cc - 1;
        float v = 0.0f;
        if (gy >= 0 && gy < Hh && gx >= 0 && gx < Ww)
            v = g_gate_in[((b * Cc + ic) * Hh + gy) * Ww + gx];
        s_in[ic * ICS_B + r * RS + cc] = v;
    }

    const int oc_base = grp * 32;
    const int pixg = tid & 31;
    const int ocq  = tid >> 5;          // 0..3
    const int px   = pixg & 15;
    const int pyb  = (pixg >> 4) << 2;  // 0,4

    ull acc2[8][2];
    #pragma unroll
    for (int k = 0; k < 8; k++) { acc2[k][0] = 0ull; acc2[k][1] = 0ull; }

    for (int cc0 = 0; cc0 < 64; cc0 += 8) {
        __syncthreads();
        for (int i = tid; i < SW_ULL; i += 128) {
            int ocl  = i / 72;
            int rest = i - ocl * 72;
            float w  = w_f[(oc_base + ocl) * 576 + cc0 * 9 + rest];
            s_w2[i] = pack2(w, w);
        }
        __syncthreads();
        #pragma unroll
        for (int icl = 0; icl < 8; icl++) {
            const float* sin = s_in + (cc0 + icl) * ICS_B + pyb * RS + px;
            const ull*   sw  = s_w2 + ocq * (8 * 72) + icl * 9;
            #pragma unroll
            for (int dx = 0; dx < 3; dx++) {
                float xr[6];
                #pragma unroll
                for (int r = 0; r < 6; r++) xr[r] = sin[r * RS + dx];
                ull xp[3][2];
                #pragma unroll
                for (int dy = 0; dy < 3; dy++) {
                    xp[dy][0] = pack2(xr[dy],     xr[dy + 1]);
                    xp[dy][1] = pack2(xr[dy + 2], xr[dy + 3]);
                }
                #pragma unroll
                for (int dy = 0; dy < 3; dy++) {
                    #pragma unroll
                    for (int k = 0; k < 8; k++) {
                        ull wp = sw[k * 72 + dy * 3 + dx];
                        ffma2(acc2[k][0], xp[dy][0], wp);
                        ffma2(acc2[k][1], xp[dy][1], wp);
                    }
                }
            }
        }
    }

    // Epilogue: GRU update + spike + outputs
    const size_t N = (size_t)Tn * Bn * Cc * HWp;
    #pragma unroll
    for (int k = 0; k < 8; k++) {
        int oc = oc_base + ocq * 8 + k;
        float bias = b_f[oc];
        #pragma unroll
        for (int j = 0; j < 2; j++) {
            float a0, a1;
            unpack2(acc2[k][j], a0, a1);
            float av[2] = {a0, a1};
            #pragma unroll
            for (int s = 0; s < 2; s++) {
                int i   = 2 * j + s;
                int gy  = ty0 + pyb + i;
                int gx  = tx0 + px;
                int pix = gy * Ww + gx;
                float xi = xt[((((size_t)t * Bn + b) * 192) + 128 + oc) * HWp + pix];
                float f  = av[s] + bias + xi;
                float ig = tanhf(f);

                size_t sidx = (size_t)(b * Cc + oc) * HWp + pix;
                float u  = g_upd[sidx];
                float hp = (t > 0) ? g_h[sidx] : 0.0f;
                float h  = (1.0f - u) * hp + u * ig;

                float thr = g_thr[b * HWp + pix];
                float d   = h - thr;
                float ev  = (d > 0.0f) ? 1.0f : 0.0f;
                float y   = ev * h;
                float nd  = (d < 0.0f) ? (thr - h) : 0.0f;

                size_t o = (((size_t)t * Bn + b) * Cc + oc) * HWp + pix;
                out[o]         = y;
                out[N + o]     = ev;
                out[2 * N + o] = nd;

                g_prev_y[sidx] = y;
                g_h[sidx]      = h - ev * thr;
            }
        }
    }
}

extern "C" void kernel_launch(void* const* d_in, const int* in_sizes, int n_in,
                              void* d_out, int out_size)
{
    const float* xt   = (const float*)d_in[0];
    const float* w_rz = (const float*)d_in[1];
    const float* b_rz = (const float*)d_in[2];
    const float* w_f  = (const float*)d_in[3];
    const float* b_f  = (const float*)d_in[4];
    float* out = (float*)d_out;

    cudaFuncSetAttribute(kA, cudaFuncAttributeMaxDynamicSharedMemorySize, SMEM_A_BYTES);
    cudaFuncSetAttribute(kB, cudaFuncAttributeMaxDynamicSharedMemorySize, SMEM_B_BYTES);

    dim3 gA(16, 4, Bn);
    dim3 gB(32, 2, Bn);
    for (int t = 0; t < Tn; t++) {
        kA<<<gA, 256, SMEM_A_BYTES>>>(xt, w_rz, b_rz, t);
        kB<<<gB, 128, SMEM_B_BYTES>>>(xt, w_f, b_f, out, t);
    }
}

// round 3
// speedup vs baseline: 1.0844x; 1.0844x over previous
#include <cuda_runtime.h>
#include <cstddef>

#define Tn 10
#define Bn 4
#define Cc 64
#define Hh 64
#define Ww 64
#define HWp 4096
#define RS 20                 // smem row stride (floats), 16B-aligned rows
#define ICS 360               // 18*RS
#define SM_IN (64*ICS)        // 23040 floats = 92160 B
#define SM_W  (8*32*12)       // 3072 floats  = 12288 B  ([icl][oc][12])
#define SMEM_BYTES ((SM_IN + SM_W)*4)   // 104448 B -> 2 blocks/SM

// Recurrent state + inter-kernel scratch (allocation-free device globals)
__device__ float g_prev_y [Bn*Cc*HWp];
__device__ float g_h      [Bn*Cc*HWp];
__device__ float g_gate_in[Bn*Cc*HWp];
__device__ float g_upd    [Bn*Cc*HWp];
__device__ float g_thr    [Bn*HWp];

__device__ __forceinline__ float sigmoidf_(float x) { return 1.0f / (1.0f + __expf(-x)); }

// 18x18 halo tile, all 64 input channels, zero-padded SAME
__device__ __forceinline__ void load_tile(const float* __restrict__ in, int b,
                                          int ty0, int tx0, float* s_in, int tid)
{
    for (int idx = tid; idx < 64 * 324; idx += 256) {
        int ic  = idx / 324;
        int rem = idx - ic * 324;
        int r   = rem / 18;
        int cc  = rem - r * 18;
        int gy  = ty0 + r - 1;
        int gx  = tx0 + cc - 1;
        float v = 0.0f;
        if (gy >= 0 && gy < Hh && gx >= 0 && gx < Ww)
            v = in[((b * Cc + ic) * Hh + gy) * Ww + gx];
        s_in[ic * ICS + r * RS + cc] = v;
    }
}

// Stage 8-ic weight chunk: s_w[icl][oc][tap] with row stride 12 (vector-friendly)
__device__ __forceinline__ void stage_w(const float* __restrict__ w, int oc_base,
                                        int cc0, float* s_w, int tid, int nthr)
{
    for (int i = tid; i < 2304; i += nthr) {
        int icl = i / 288;
        int rem = i - icl * 288;
        int oc  = rem / 9;
        int tap = rem - oc * 9;
        s_w[icl * 384 + oc * 12 + tap] = w[(oc_base + oc) * 576 + (cc0 + icl) * 9 + tap];
    }
}

// Inner MAC: 8 oc x 3x3 taps x 4 px from registers
__device__ __forceinline__ void mac_chunk(const float* s_in, const float* s_w,
                                          int cc0, int py, int xb, int ocq,
                                          float acc[8][4])
{
    #pragma unroll
    for (int icl = 0; icl < 8; icl++) {
        const float* sin = s_in + (cc0 + icl) * ICS + py * RS + xb;
        float x[3][8];
        #pragma unroll
        for (int dy = 0; dy < 3; dy++) {
            float4 a = *(const float4*)(sin + dy * RS);
            float4 b4 = *(const float4*)(sin + dy * RS + 4);
            x[dy][0]=a.x; x[dy][1]=a.y; x[dy][2]=a.z; x[dy][3]=a.w;
            x[dy][4]=b4.x; x[dy][5]=b4.y; x[dy][6]=b4.z; x[dy][7]=b4.w;
        }
        const float* sw = s_w + icl * 384 + (ocq * 8) * 12;
        #pragma unroll
        for (int k = 0; k < 8; k++) {
            float4 w0 = *(const float4*)(sw + k * 12);
            float4 w1 = *(const float4*)(sw + k * 12 + 4);
            float  w8 = sw[k * 12 + 8];
            float wv[9] = {w0.x, w0.y, w0.z, w0.w, w1.x, w1.y, w1.z, w1.w, w8};
            #pragma unroll
            for (int dy = 0; dy < 3; dy++)
                #pragma unroll
                for (int dx = 0; dx < 3; dx++) {
                    float wt = wv[dy * 3 + dx];
                    #pragma unroll
                    for (int p = 0; p < 4; p++)
                        acc[k][p] += wt * x[dy][dx + p];
                }
        }
    }
}

// ---------------------------------------------------------------------------
// Kernel A: rz = conv3x3(prev_y, w_rz) + b_rz; gates; thr channel in grp 0
// grid (16 tiles 16x16, 4 oc-groups, 4 batch), 256 threads
// ---------------------------------------------------------------------------
__global__ void __launch_bounds__(256, 2)
kA(const float* __restrict__ xt, const float* __restrict__ w_rz,
   const float* __restrict__ b_rz, int t)
{
    extern __shared__ float smem[];
    float* s_in = smem;
    float* s_w  = smem + SM_IN;

    const int tid  = threadIdx.x;
    const int tile = blockIdx.x;
    const int grp  = blockIdx.y;
    const int b    = blockIdx.z;
    const int ty0  = (tile >> 2) * 16;
    const int tx0  = (tile & 3) * 16;

    if (t > 0) load_tile(g_prev_y, b, ty0, tx0, s_in, tid);

    const int oc_base = grp * 32;
    const int ocq = tid >> 6;          // 0..3, warp-uniform
    const int pg  = tid & 63;
    const int py  = pg >> 2;           // 0..15
    const int xb  = (pg & 3) * 4;      // 0,4,8,12

    float acc[8][4];
    #pragma unroll
    for (int k = 0; k < 8; k++)
        #pragma unroll
        for (int p = 0; p < 4; p++) acc[k][p] = 0.0f;

    if (t > 0) {
        for (int cc0 = 0; cc0 < 64; cc0 += 8) {
            __syncthreads();
            stage_w(w_rz, oc_base, cc0, s_w, tid, 256);
            __syncthreads();
            mac_chunk(s_in, s_w, cc0, py, xb, ocq, acc);
        }
    }

    // Epilogue: gates
    #pragma unroll
    for (int k = 0; k < 8; k++) {
        int oc = oc_base + ocq * 8 + k;
        float bias = b_rz[oc];
        #pragma unroll
        for (int p = 0; p < 4; p++) {
            int gx  = tx0 + xb + p;
            int gy  = ty0 + py;
            int pix = gy * Ww + gx;
            float xi = xt[((((size_t)t * Bn + b) * 192) + oc) * HWp + pix];
            float sg = sigmoidf_(acc[k][p] + bias + xi);
            if (oc < 64) {
                g_upd[(b * Cc + oc) * HWp + pix] = sg;
            } else {
                int c = oc - 64;
                float pyv = 0.0f;
                if (t > 0)
                    pyv = s_in[c * ICS + (py + 1) * RS + (xb + p + 1)];
                g_gate_in[(b * Cc + c) * HWp + pix] = pyv * sg;
            }
        }
    }

    // Threshold channel (oc 128), grp 0 only
    if (grp == 0) {
        float accT = 0.0f;
        const int px1 = tid & 15, py1 = tid >> 4;
        if (t > 0) {
            __syncthreads();
            for (int i = tid; i < 576; i += 256)
                s_w[i] = w_rz[128 * 576 + i];
            __syncthreads();
            float a0 = 0.f, a1 = 0.f, a2 = 0.f;
            for (int ic = 0; ic < 64; ic++) {
                const float* sin = s_in + ic * ICS + py1 * RS + px1;
                const float* sw  = s_w + ic * 9;
                a0 += sw[0]*sin[0]      + sw[3]*sin[RS]     + sw[6]*sin[2*RS];
                a1 += sw[1]*sin[1]      + sw[4]*sin[RS+1]   + sw[7]*sin[2*RS+1];
                a2 += sw[2]*sin[2]      + sw[5]*sin[RS+2]   + sw[8]*sin[2*RS+2];
            }
            accT = a0 + a1 + a2;
        }
        g_thr[b * HWp + (ty0 + py1) * Ww + (tx0 + px1)] = sigmoidf_(accT + b_rz[128]);
    }
}

// ---------------------------------------------------------------------------
// Kernel B: f = conv3x3(gate_in, w_f) + b_f + xi_f; GRU update + spike + out
// grid (16 tiles 16x16, 2 oc-groups, 4 batch), 256 threads
// ---------------------------------------------------------------------------
__global__ void __launch_bounds__(256, 2)
kB(const float* __restrict__ xt, const float* __restrict__ w_f,
   const float* __restrict__ b_f, float* __restrict__ out, int t)
{
    extern __shared__ float smem[];
    float* s_in = smem;
    float* s_w  = smem + SM_IN;

    const int tid  = threadIdx.x;
    const int tile = blockIdx.x;
    const int grp  = blockIdx.y;
    const int b    = blockIdx.z;
    const int ty0  = (tile >> 2) * 16;
    const int tx0  = (tile & 3) * 16;

    load_tile(g_gate_in, b, ty0, tx0, s_in, tid);

    const int oc_base = grp * 32;
    const int ocq = tid >> 6;
    const int pg  = tid & 63;
    const int py  = pg >> 2;
    const int xb  = (pg & 3) * 4;

    float acc[8][4];
    #pragma unroll
    for (int k = 0; k < 8; k++)
        #pragma unroll
        for (int p = 0; p < 4; p++) acc[k][p] = 0.0f;

    for (int cc0 = 0; cc0 < 64; cc0 += 8) {
        __syncthreads();
        stage_w(w_f, oc_base, cc0, s_w, tid, 256);
        __syncthreads();
        mac_chunk(s_in, s_w, cc0, py, xb, ocq, acc);
    }

    // Epilogue: GRU update + spike + outputs
    const size_t N = (size_t)Tn * Bn * Cc * HWp;
    #pragma unroll
    for (int k = 0; k < 8; k++) {
        int oc = oc_base + ocq * 8 + k;
        float bias = b_f[oc];
        #pragma unroll
        for (int p = 0; p < 4; p++) {
            int gx  = tx0 + xb + p;
            int gy  = ty0 + py;
            int pix = gy * Ww + gx;
            float xi = xt[((((size_t)t * Bn + b) * 192) + 128 + oc) * HWp + pix];
            float f  = acc[k][p] + bias + xi;
            float ig = tanhf(f);

            size_t sidx = (size_t)(b * Cc + oc) * HWp + pix;
            float u  = g_upd[sidx];
            float hp = (t > 0) ? g_h[sidx] : 0.0f;
            float h  = (1.0f - u) * hp + u * ig;

            float thr = g_thr[b * HWp + pix];
            float d   = h - thr;
            float ev  = (d > 0.0f) ? 1.0f : 0.0f;
            float y   = ev * h;
            float nd  = (d < 0.0f) ? (thr - h) : 0.0f;

            size_t o = (((size_t)t * Bn + b) * Cc + oc) * HWp + pix;
            out[o]         = y;
            out[N + o]     = ev;
            out[2 * N + o] = nd;

            g_prev_y[sidx] = y;
            g_h[sidx]      = h - ev * thr;
        }
    }
}

extern "C" void kernel_launch(void* const* d_in, const int* in_sizes, int n_in,
                              void* d_out, int out_size)
{
    const float* xt   = (const float*)d_in[0];
    const float* w_rz = (const float*)d_in[1];
    const float* b_rz = (const float*)d_in[2];
    const float* w_f  = (const float*)d_in[3];
    const float* b_f  = (const float*)d_in[4];
    float* out = (float*)d_out;

    cudaFuncSetAttribute(kA, cudaFuncAttributeMaxDynamicSharedMemorySize, SMEM_BYTES);
    cudaFuncSetAttribute(kB, cudaFuncAttributeMaxDynamicSharedMemorySize, SMEM_BYTES);

    dim3 gA(16, 4, Bn);
    dim3 gB(16, 2, Bn);
    for (int t = 0; t < Tn; t++) {
        kA<<<gA, 256, SMEM_BYTES>>>(xt, w_rz, b_rz, t);
        kB<<<gB, 256, SMEM_BYTES>>>(xt, w_f, b_f, out, t);
    }
}